// round 15
// baseline (speedup 1.0000x reference)
#include <cuda_runtime.h>
#include <cstdint>
#include <math.h>
#include <float.h>

#define N_NODES 50000
#define E_EDGES 800000
#define F_IN    128
#define HID     64
#define HEADS   4
#define OUTC    32
#define HC0     (HEADS*HID)   /* 256 */

// ---------------- scratch (static device globals; no allocation) ----------------
__device__ float g_hu [N_NODES * HID];
__device__ float g_hi [N_NODES * HID];
__device__ float g_hs [N_NODES * HC0];      // u2i agg scratch
__device__ float g_hs2[N_NODES * HC0];      // i2u agg scratch
__device__ float g_hu1[N_NODES * HC0];      // l1 GEMM outputs (2 x [N,32]) live here
__device__ float g_al0[16 * N_NODES];       // l0 logits: [A|B|C|D], each [N*4]
__device__ float g_al1[4 * N_NODES];        // l1 logits: [A|B|C|D], each [N]
__device__ float g_vbuf[8 * 512];
__device__ int   g_cnt [2 * N_NODES];       // zero-init; self-cleared by scan1
__device__ int   g_rank_u2i[E_EDGES];
__device__ int   g_rank_i2u[E_EDGES];
__device__ int   g_row_u2i[N_NODES + 1];
__device__ int   g_row_i2u[N_NODES + 1];
__device__ int   g_src_u2i[E_EDGES];
__device__ int   g_src_i2u[E_EDGES];

__device__ __forceinline__ float lrelu(float a) { return (a > 0.f) ? a : 0.2f * a; }

__device__ __forceinline__ uint32_t f2tf32(float f) {
    uint32_t u;
    asm("cvt.rna.tf32.f32 %0, %1;" : "=r"(u) : "f"(f));
    return u;
}
__device__ __forceinline__ void mma_tf32(float c[4], const uint32_t a[4],
                                         uint32_t b0, uint32_t b1) {
    asm volatile("mma.sync.aligned.m16n8k8.row.col.f32.tf32.tf32.f32 "
        "{%0,%1,%2,%3}, {%4,%5,%6,%7}, {%8,%9}, {%0,%1,%2,%3};"
        : "+f"(c[0]), "+f"(c[1]), "+f"(c[2]), "+f"(c[3])
        : "r"(a[0]), "r"(a[1]), "r"(a[2]), "r"(a[3]), "r"(b0), "r"(b1));
}

// ---------------- job descriptors ----------------
struct GemmJobs {
    const float* A[2];
    const float* B[2];
    const float* bias[2];
    float*       C[2];
    const float* vs[2];
    const float* vd[2];
    float*       alS[2];
    float*       alD[2];
};
struct FuseJobs {
    const float* A[2];
    const float* W1[2];
    const float* b1[2];
    const float* vs[2];
    const float* vd[2];
    float*       alS[2];
    float*       alD[2];
    const float* W2[2];
    float*       C2[2];
};
struct PrepJobs {
    const float* ws[4]; const float* as_[4];
    const float* wd[4]; const float* ad_[4];
    float* vs[4]; float* vd[4];
    int H[4]; int C[4];
};

// =====================================================================
// Projection GEMM (tf32): C = ELU(A[M,128] @ B[128,64] + bias),
// fused layer-0 logits: cross-warp smem combine + plain store.
// =====================================================================
__global__ __launch_bounds__(256)
void mma_gemm_proj(GemmJobs jobs, int M)
{
    constexpr int BM = 128, BN = 64, BK = 32, K = F_IN;
    constexpr int THREADS = 256;
    constexpr int ASTR = 36;
    constexpr int BSTR = BN + 8;

    __shared__ uint32_t As[BM*ASTR];
    __shared__ uint32_t Bs[BK*BSTR];
    __shared__ float    sCmb[2][4][2][2][8][4];

    const int z = blockIdx.z;
    const float* __restrict__ A    = jobs.A[z];
    const float* __restrict__ B    = jobs.B[z];
    const float* __restrict__ bias = jobs.bias[z];
    float*       __restrict__ C    = jobs.C[z];
    const float* __restrict__ vs   = jobs.vs[z];
    const float* __restrict__ vd   = jobs.vd[z];
    float*       __restrict__ alS  = jobs.alS[z];
    float*       __restrict__ alD  = jobs.alD[z];

    const int tid  = threadIdx.x;
    const int wid  = tid >> 5;
    const int lane = tid & 31;
    const int g = lane >> 2, t = lane & 3;
    const int warpM = wid & 3;
    const int warpN = wid >> 2;
    const int rowBase = blockIdx.y * BM;

    float acc[2][4][4] = {};

    for (int k0 = 0; k0 < K; k0 += BK) {
        #pragma unroll
        for (int it = 0; it < (BM*BK/4)/THREADS; it++) {
            int idx = tid + it*THREADS;
            int m  = idx >> 3;
            int kv = idx & 7;
            int gm = rowBase + m;
            float4 v = make_float4(0.f,0.f,0.f,0.f);
            if (gm < M) v = *(const float4*)&A[(size_t)gm*K + k0 + kv*4];
            *(uint4*)&As[m*ASTR + kv*4] =
                make_uint4(f2tf32(v.x), f2tf32(v.y), f2tf32(v.z), f2tf32(v.w));
        }
        #pragma unroll
        for (int it = 0; it < (BK*BN/4)/THREADS; it++) {
            int idx = tid + it*THREADS;
            int kk = idx / (BN/4);
            int nv = idx % (BN/4);
            float4 v = *(const float4*)&B[(size_t)(k0+kk)*BN + nv*4];
            *(uint4*)&Bs[kk*BSTR + nv*4] =
                make_uint4(f2tf32(v.x), f2tf32(v.y), f2tf32(v.z), f2tf32(v.w));
        }
        __syncthreads();

        #pragma unroll
        for (int ks = 0; ks < BK/8; ks++) {
            int kb = ks*8;
            uint32_t a[2][4];
            #pragma unroll
            for (int mf = 0; mf < 2; mf++) {
                int m0 = warpM*32 + mf*16 + g;
                a[mf][0] = As[m0*ASTR     + kb + t];
                a[mf][1] = As[(m0+8)*ASTR + kb + t];
                a[mf][2] = As[m0*ASTR     + kb + t + 4];
                a[mf][3] = As[(m0+8)*ASTR + kb + t + 4];
            }
            #pragma unroll
            for (int nf = 0; nf < 4; nf++) {
                int n0 = warpN*32 + nf*8 + g;
                uint32_t b0 = Bs[(kb+t)*BSTR   + n0];
                uint32_t b1 = Bs[(kb+t+4)*BSTR + n0];
                mma_tf32(acc[0][nf], a[0], b0, b1);
                mma_tf32(acc[1][nf], a[1], b0, b1);
            }
        }
        __syncthreads();
    }

    float aSa[2][2][4] = {}, aDa[2][2][4] = {};
    #pragma unroll
    for (int mf = 0; mf < 2; mf++) {
        #pragma unroll
        for (int rr = 0; rr < 2; rr++) {
            int row = rowBase + warpM*32 + mf*16 + rr*8 + g;
            bool ok = row < M;
            #pragma unroll
            for (int nf = 0; nf < 4; nf++) {
                int col = warpN*32 + nf*8 + 2*t;
                float v0 = acc[mf][nf][rr*2 + 0] + bias[col];
                float v1 = acc[mf][nf][rr*2 + 1] + bias[col + 1];
                v0 = (v0 > 0.f) ? v0 : (expf(v0) - 1.f);
                v1 = (v1 > 0.f) ? v1 : (expf(v1) - 1.f);
                if (ok) *(float2*)&C[(size_t)row*BN + col] = make_float2(v0, v1);
                #pragma unroll
                for (int h = 0; h < 4; h++) {
                    aSa[mf][rr][h] = fmaf(v0, vs[col*4 + h],     aSa[mf][rr][h]);
                    aSa[mf][rr][h] = fmaf(v1, vs[(col+1)*4 + h], aSa[mf][rr][h]);
                    aDa[mf][rr][h] = fmaf(v0, vd[col*4 + h],     aDa[mf][rr][h]);
                    aDa[mf][rr][h] = fmaf(v1, vd[(col+1)*4 + h], aDa[mf][rr][h]);
                }
            }
            #pragma unroll
            for (int h = 0; h < 4; h++) {
                aSa[mf][rr][h] += __shfl_xor_sync(0xffffffffu, aSa[mf][rr][h], 1);
                aSa[mf][rr][h] += __shfl_xor_sync(0xffffffffu, aSa[mf][rr][h], 2);
                aDa[mf][rr][h] += __shfl_xor_sync(0xffffffffu, aDa[mf][rr][h], 1);
                aDa[mf][rr][h] += __shfl_xor_sync(0xffffffffu, aDa[mf][rr][h], 2);
            }
        }
    }
    if (warpN == 1 && t == 0) {
        #pragma unroll
        for (int mf = 0; mf < 2; mf++)
            #pragma unroll
            for (int rr = 0; rr < 2; rr++)
                #pragma unroll
                for (int h = 0; h < 4; h++) {
                    sCmb[0][warpM][mf][rr][g][h] = aSa[mf][rr][h];
                    sCmb[1][warpM][mf][rr][g][h] = aDa[mf][rr][h];
                }
    }
    __syncthreads();
    if (warpN == 0 && t == 0) {
        #pragma unroll
        for (int mf = 0; mf < 2; mf++) {
            #pragma unroll
            for (int rr = 0; rr < 2; rr++) {
                int row = rowBase + warpM*32 + mf*16 + rr*8 + g;
                if (row < M) {
                    #pragma unroll
                    for (int h = 0; h < 4; h++) {
                        alS[row*4 + h] = aSa[mf][rr][h] + sCmb[0][warpM][mf][rr][g][h];
                        alD[row*4 + h] = aDa[mf][rr][h] + sCmb[1][warpM][mf][rr][g][h];
                    }
                }
            }
        }
    }
}

// =====================================================================
// FUSED head-GEMM chain + l1-GEMM (hi1/hu1 never touch global memory).
// =====================================================================
__global__ __launch_bounds__(256)
void head_l1_gemm(FuseJobs jobs, int M)
{
    constexpr int BM = 128;
    constexpr int ASTR = 36, BSTR = 72, C1STR = 68, B2STR = 40;
    extern __shared__ uint32_t sm[];
    uint32_t* As  = sm;
    uint32_t* Bs  = As  + BM*ASTR;
    uint32_t* C1s = Bs  + 32*BSTR;
    uint32_t* B2s = C1s + 128*C1STR;
    __shared__ float sS2[4][2][2][8], sD2[4][2][2][8];

    const int z = blockIdx.z;
    const float* __restrict__ A   = jobs.A[z];
    const float* __restrict__ W1  = jobs.W1[z];
    const float* __restrict__ b1  = jobs.b1[z];
    const float* __restrict__ vs  = jobs.vs[z];
    const float* __restrict__ vd  = jobs.vd[z];
    float*       __restrict__ alS = jobs.alS[z];
    float*       __restrict__ alD = jobs.alD[z];
    const float* __restrict__ W2  = jobs.W2[z];
    float*       __restrict__ C2  = jobs.C2[z];

    const int tid  = threadIdx.x;
    const int wid  = tid >> 5;
    const int lane = tid & 31;
    const int g = lane >> 2, t = lane & 3;
    const int warpM = wid & 3;
    const int warpN = wid >> 2;
    const int rowBase = blockIdx.y * BM;

    float acc2[2][2][4] = {};
    float aS[2][2] = {}, aD[2][2] = {};

    for (int h = 0; h < 4; h++) {
        float acc[2][4][4] = {};
        for (int k0 = 0; k0 < 64; k0 += 32) {
            #pragma unroll
            for (int it = 0; it < 4; it++) {
                int idx = tid + it*256;
                int m  = idx >> 3;
                int kv = idx & 7;
                int gm = rowBase + m;
                float4 v = make_float4(0.f,0.f,0.f,0.f);
                if (gm < M) v = *(const float4*)&A[(size_t)gm*HC0 + h*64 + k0 + kv*4];
                *(uint4*)&As[m*ASTR + kv*4] =
                    make_uint4(f2tf32(v.x), f2tf32(v.y), f2tf32(v.z), f2tf32(v.w));
            }
            #pragma unroll
            for (int it = 0; it < 2; it++) {
                int idx = tid + it*256;
                int kk = idx / 16;
                int nv = idx % 16;
                float4 v = *(const float4*)&W1[(size_t)(k0+kk)*HC0 + h*64 + nv*4];
                *(uint4*)&Bs[kk*BSTR + nv*4] =
                    make_uint4(f2tf32(v.x), f2tf32(v.y), f2tf32(v.z), f2tf32(v.w));
            }
            __syncthreads();
            #pragma unroll
            for (int ks = 0; ks < 4; ks++) {
                int kb = ks*8;
                uint32_t a[2][4];
                #pragma unroll
                for (int mf = 0; mf < 2; mf++) {
                    int m0 = warpM*32 + mf*16 + g;
                    a[mf][0] = As[m0*ASTR     + kb + t];
                    a[mf][1] = As[(m0+8)*ASTR + kb + t];
                    a[mf][2] = As[m0*ASTR     + kb + t + 4];
                    a[mf][3] = As[(m0+8)*ASTR + kb + t + 4];
                }
                #pragma unroll
                for (int nf = 0; nf < 4; nf++) {
                    int n0 = warpN*32 + nf*8 + g;
                    uint32_t b0 = Bs[(kb+t)*BSTR   + n0];
                    uint32_t bb = Bs[(kb+t+4)*BSTR + n0];
                    mma_tf32(acc[0][nf], a[0], b0, bb);
                    mma_tf32(acc[1][nf], a[1], b0, bb);
                }
            }
            __syncthreads();
        }

        #pragma unroll
        for (int mf = 0; mf < 2; mf++) {
            #pragma unroll
            for (int rr = 0; rr < 2; rr++) {
                int rl = warpM*32 + mf*16 + rr*8 + g;
                #pragma unroll
                for (int nf = 0; nf < 4; nf++) {
                    int col = warpN*32 + nf*8 + 2*t;
                    float v0 = acc[mf][nf][rr*2 + 0] + b1[h*64 + col];
                    float v1 = acc[mf][nf][rr*2 + 1] + b1[h*64 + col + 1];
                    v0 = (v0 > 0.f) ? v0 : (expf(v0) - 1.f);
                    v1 = (v1 > 0.f) ? v1 : (expf(v1) - 1.f);
                    aS[mf][rr] = fmaf(v0, vs[h*64 + col],     aS[mf][rr]);
                    aS[mf][rr] = fmaf(v1, vs[h*64 + col + 1], aS[mf][rr]);
                    aD[mf][rr] = fmaf(v0, vd[h*64 + col],     aD[mf][rr]);
                    aD[mf][rr] = fmaf(v1, vd[h*64 + col + 1], aD[mf][rr]);
                    C1s[rl*C1STR + col]     = f2tf32(v0);
                    C1s[rl*C1STR + col + 1] = f2tf32(v1);
                }
            }
        }
        #pragma unroll
        for (int it = 0; it < 2; it++) {
            int idx = tid + it*256;
            int kk = idx / 8;
            int nv = idx % 8;
            float4 v = *(const float4*)&W2[(size_t)(h*64 + kk)*OUTC + nv*4];
            *(uint4*)&B2s[kk*B2STR + nv*4] =
                make_uint4(f2tf32(v.x), f2tf32(v.y), f2tf32(v.z), f2tf32(v.w));
        }
        __syncthreads();

        #pragma unroll
        for (int ks = 0; ks < 8; ks++) {
            int kb = ks*8;
            uint32_t a2[2][4];
            #pragma unroll
            for (int mf = 0; mf < 2; mf++) {
                int m0 = warpM*32 + mf*16 + g;
                a2[mf][0] = C1s[m0*C1STR     + kb + t];
                a2[mf][1] = C1s[(m0+8)*C1STR + kb + t];
                a2[mf][2] = C1s[m0*C1STR     + kb + t + 4];
                a2[mf][3] = C1s[(m0+8)*C1STR + kb + t + 4];
            }
            #pragma unroll
            for (int nf2 = 0; nf2 < 2; nf2++) {
                int n0 = warpN*16 + nf2*8 + g;
                uint32_t b0 = B2s[(kb+t)*B2STR   + n0];
                uint32_t bb = B2s[(kb+t+4)*B2STR + n0];
                mma_tf32(acc2[0][nf2], a2[0], b0, bb);
                mma_tf32(acc2[1][nf2], a2[1], b0, bb);
            }
        }
        __syncthreads();
    }

    #pragma unroll
    for (int mf = 0; mf < 2; mf++)
        #pragma unroll
        for (int rr = 0; rr < 2; rr++) {
            aS[mf][rr] += __shfl_xor_sync(0xffffffffu, aS[mf][rr], 1);
            aS[mf][rr] += __shfl_xor_sync(0xffffffffu, aS[mf][rr], 2);
            aD[mf][rr] += __shfl_xor_sync(0xffffffffu, aD[mf][rr], 1);
            aD[mf][rr] += __shfl_xor_sync(0xffffffffu, aD[mf][rr], 2);
        }
    if (warpN == 1 && t == 0) {
        #pragma unroll
        for (int mf = 0; mf < 2; mf++)
            #pragma unroll
            for (int rr = 0; rr < 2; rr++) {
                sS2[warpM][mf][rr][g] = aS[mf][rr];
                sD2[warpM][mf][rr][g] = aD[mf][rr];
            }
    }
    __syncthreads();

    #pragma unroll
    for (int mf = 0; mf < 2; mf++) {
        #pragma unroll
        for (int rr = 0; rr < 2; rr++) {
            int row = rowBase + warpM*32 + mf*16 + rr*8 + g;
            bool ok = row < M;
            if (warpN == 0 && t == 0 && ok) {
                alS[row] = aS[mf][rr] + sS2[warpM][mf][rr][g];
                alD[row] = aD[mf][rr] + sD2[warpM][mf][rr][g];
            }
            #pragma unroll
            for (int nf2 = 0; nf2 < 2; nf2++) {
                int col = warpN*16 + nf2*8 + 2*t;
                float v0 = acc2[mf][nf2][rr*2 + 0];
                float v1 = acc2[mf][nf2][rr*2 + 1];
                if (ok) *(float2*)&C2[(size_t)row*OUTC + col] = make_float2(v0, v1);
            }
        }
    }
}

// ---------------- streams + events + smem attr (created pre-checkpoint) ---------
static cudaStream_t g_s2, g_s3;
static cudaEvent_t  g_evF, g_evJ2, g_evJ3;
static int g_stream_init = []() {
    cudaStreamCreateWithFlags(&g_s2, cudaStreamNonBlocking);
    cudaStreamCreateWithFlags(&g_s3, cudaStreamNonBlocking);
    cudaEventCreateWithFlags(&g_evF,  cudaEventDisableTiming);
    cudaEventCreateWithFlags(&g_evJ2, cudaEventDisableTiming);
    cudaEventCreateWithFlags(&g_evJ3, cudaEventDisableTiming);
    cudaFuncSetAttribute(head_l1_gemm, cudaFuncAttributeMaxDynamicSharedMemorySize, 72704);
    return 0;
}();

// =====================================================================
// Warp-parallel attention-vector prep: one warp per output element.
// 4 jobs x 256 outputs = 1024 warps -> 128 blocks x 256 threads.
// =====================================================================
__global__ __launch_bounds__(256)
void prep_warp(PrepJobs pj)
{
    int gw   = (blockIdx.x * blockDim.x + threadIdx.x) >> 5;   // 0..1023
    int lane = threadIdx.x & 31;
    int j    = gw >> 8;          // job 0..3
    int idx  = gw & 255;         // output index within job
    int H = pj.H[j], C = pj.C[j];
    int k = idx / H, h = idx % H;
    const float* wsp = pj.ws[j] + (size_t)k*(H*C) + h*C;
    const float* wdp = pj.wd[j] + (size_t)k*(H*C) + h*C;
    const float* asp = pj.as_[j] + h*C;
    const float* adp = pj.ad_[j] + h*C;
    float s1 = 0.f, s2 = 0.f;
    for (int c = lane; c < C; c += 32) {
        s1 = fmaf(wsp[c], asp[c], s1);
        s2 = fmaf(wdp[c], adp[c], s2);
    }
    #pragma unroll
    for (int o = 16; o; o >>= 1) {
        s1 += __shfl_xor_sync(0xffffffffu, s1, o);
        s2 += __shfl_xor_sync(0xffffffffu, s2, o);
    }
    if (lane == 0) {
        pj.vs[j][k*H + h] = s1;
        pj.vd[j][k*H + h] = s2;
    }
}

// =====================================================================
// CSR build, per edge set (two streams run these concurrently)
// =====================================================================
__global__ void hist1(const int* __restrict__ dst, int* __restrict__ cnt,
                      int* __restrict__ rank, int E)
{
    int e = 2 * (blockIdx.x * blockDim.x + threadIdx.x);
    if (e < E) {
        rank[e]     = atomicAdd(&cnt[dst[e]], 1);
        rank[e + 1] = atomicAdd(&cnt[dst[e + 1]], 1);
    }
}
// monolithic per-set scan (1 block); zeroes cnt after reading (self-clear)
__global__ void scan1(int* __restrict__ cnt, int* __restrict__ row, int n)
{
    __shared__ int wsum[32];
    __shared__ int s_carry;
    int tid = threadIdx.x, lane = tid & 31, warp = tid >> 5;
    if (tid == 0) s_carry = 0;
    __syncthreads();
    for (int base = 0; base < n; base += 1024) {
        int v = 0;
        if (base + tid < n) {
            v = cnt[base + tid];
            cnt[base + tid] = 0;
        }
        int s = v;
        #pragma unroll
        for (int o = 1; o < 32; o <<= 1) {
            int t = __shfl_up_sync(0xffffffffu, s, o);
            if (lane >= o) s += t;
        }
        if (lane == 31) wsum[warp] = s;
        __syncthreads();
        if (warp == 0) {
            int ws = wsum[lane];
            #pragma unroll
            for (int o = 1; o < 32; o <<= 1) {
                int t = __shfl_up_sync(0xffffffffu, ws, o);
                if (lane >= o) ws += t;
            }
            wsum[lane] = ws;
        }
        __syncthreads();
        int carry = s_carry;
        int incl  = s + (warp > 0 ? wsum[warp - 1] : 0);
        if (base + tid < n) row[base + tid] = carry + incl - v;
        __syncthreads();
        if (tid == 1023) s_carry = carry + wsum[31];
        __syncthreads();
    }
    if (tid == 0) row[n] = s_carry;
}
// fill: 8 edges per thread (E % 8 == 0)
__global__ void fill1(const int* __restrict__ s, const int* __restrict__ d,
                      const int* __restrict__ rank, const int* __restrict__ row,
                      int* __restrict__ out, int E)
{
    int e = 8 * (blockIdx.x * blockDim.x + threadIdx.x);
    if (e >= E) return;
    int4 da = *(const int4*)&d[e],     db = *(const int4*)&d[e+4];
    int4 ra = *(const int4*)&rank[e],  rb = *(const int4*)&rank[e+4];
    int4 sa = *(const int4*)&s[e],     sb = *(const int4*)&s[e+4];
    int pa0 = row[da.x], pa1 = row[da.y], pa2 = row[da.z], pa3 = row[da.w];
    int pb0 = row[db.x], pb1 = row[db.y], pb2 = row[db.z], pb3 = row[db.w];
    out[pa0 + ra.x] = sa.x; out[pa1 + ra.y] = sa.y;
    out[pa2 + ra.z] = sa.z; out[pa3 + ra.w] = sa.w;
    out[pb0 + rb.x] = sb.x; out[pb1 + rb.y] = sb.y;
    out[pb2 + rb.z] = sb.z; out[pb3 + rb.w] = sb.w;
}

// =====================================================================
// Layer-0 aggregation (both directions), single pass, 2 edges/iter.
// =====================================================================
__global__ void gat_agg_l0_2(const int* __restrict__ rowA, const int* __restrict__ srcA,
                             const float* __restrict__ alsA, const float* __restrict__ aldA,
                             const float* __restrict__ xA, float* __restrict__ outA,
                             const int* __restrict__ rowB, const int* __restrict__ srcB,
                             const float* __restrict__ alsB, const float* __restrict__ aldB,
                             const float* __restrict__ xB, float* __restrict__ outB,
                             int N)
{
    __shared__ float4 sh_ea[4][32];
    __shared__ int    sh_s [4][32];

    int gw   = (blockIdx.x * blockDim.x + threadIdx.x) >> 5;
    int w    = (threadIdx.x >> 5) & 3;
    int lane = threadIdx.x & 31;
    int half = lane >> 4;
    int q    = lane & 15;
    if (gw >= 2*N) return;
    int dir = (gw >= N);
    int d   = dir ? gw - N : gw;
    const int*   row_ptr = dir ? rowB : rowA;
    const int*   csr_src = dir ? srcB : srcA;
    const float* als     = dir ? alsB : alsA;
    const float* ald     = dir ? aldB : aldA;
    const float* x       = dir ? xB   : xA;
    float*       agg     = dir ? outB : outA;

    int ro = row_ptr[d], re = row_ptr[d + 1];
    float4 adv = ((const float4*)ald)[d];
    float ad[4] = {adv.x, adv.y, adv.z, adv.w};

    float acc[4][4] = {};
    float den[4] = {};

    for (int base = ro; base < re; base += 32) {
        int idx = base + lane;
        int s = 0;
        float4 ea4 = make_float4(0.f, 0.f, 0.f, 0.f);
        if (idx < re) {
            s = csr_src[idx];
            float4 av = ((const float4*)als)[s];
            ea4.x = __expf(lrelu(av.x + ad[0]));
            ea4.y = __expf(lrelu(av.y + ad[1]));
            ea4.z = __expf(lrelu(av.z + ad[2]));
            ea4.w = __expf(lrelu(av.w + ad[3]));
        }
        den[0] += ea4.x; den[1] += ea4.y; den[2] += ea4.z; den[3] += ea4.w;
        sh_ea[w][lane] = ea4;
        sh_s [w][lane] = s;
        __syncwarp();

        int cnt = min(32, re - base);
        int npair = (cnt + 1) >> 1;
        #pragma unroll 4
        for (int j = 0; j < npair; j++) {
            int jj = 2*j + half;
            float4 e4 = sh_ea[w][jj];
            int    sj = sh_s [w][jj];
            float  e[4] = {e4.x, e4.y, e4.z, e4.w};
            float4 xv = *(const float4*)(x + (size_t)sj * HID + q*4);
            float  xr[4] = {xv.x, xv.y, xv.z, xv.w};
            #pragma unroll
            for (int h = 0; h < 4; h++)
                #pragma unroll
                for (int c = 0; c < 4; c++)
                    acc[h][c] = fmaf(e[h], xr[c], acc[h][c]);
        }
        __syncwarp();
    }
    #pragma unroll
    for (int h = 0; h < 4; h++) {
        #pragma unroll
        for (int c = 0; c < 4; c++)
            acc[h][c] += __shfl_xor_sync(0xffffffffu, acc[h][c], 16);
        #pragma unroll
        for (int o = 16; o; o >>= 1)
            den[h] += __shfl_xor_sync(0xffffffffu, den[h], o);
    }

    int h0 = 2*half;
    #pragma unroll
    for (int hh = 0; hh < 2; hh++) {
        int h = h0 + hh;
        float inv = 1.f / (den[h] + 1e-16f);
        float4 o4 = make_float4(acc[h][0]*inv, acc[h][1]*inv,
                                acc[h][2]*inv, acc[h][3]*inv);
        *(float4*)&agg[(size_t)d*HC0 + h*HID + q*4] = o4;
    }
}

// =====================================================================
// Layer-1 aggregation (both directions), single pass, 4 edges/iter.
// =====================================================================
__global__ void gat_agg_l1_2(const int* __restrict__ rowA, const int* __restrict__ srcA,
                             const float* __restrict__ alsA, const float* __restrict__ aldA,
                             const float* __restrict__ hsA, const float* __restrict__ biasA,
                             float* __restrict__ outA,
                             const int* __restrict__ rowB, const int* __restrict__ srcB,
                             const float* __restrict__ alsB, const float* __restrict__ aldB,
                             const float* __restrict__ hsB, const float* __restrict__ biasB,
                             float* __restrict__ outB,
                             int N)
{
    __shared__ float sh_ea[4][32];
    __shared__ int   sh_s [4][32];

    int gw   = (blockIdx.x * blockDim.x + threadIdx.x) >> 5;
    int w    = (threadIdx.x >> 5) & 3;
    int lane = threadIdx.x & 31;
    int grp  = lane >> 3;
    int q    = lane & 7;
    if (gw >= 2*N) return;
    int dir = (gw >= N);
    int d   = dir ? gw - N : gw;
    const int*   row_ptr = dir ? rowB  : rowA;
    const int*   csr_src = dir ? srcB  : srcA;
    const float* als     = dir ? alsB  : alsA;
    const float* ald     = dir ? aldB  : aldA;
    const float* hs      = dir ? hsB   : hsA;
    const float* bias    = dir ? biasB : biasA;
    float*       out     = dir ? outB  : outA;

    int ro = row_ptr[d], re = row_ptr[d + 1];
    float aldh = ald[d];

    float acc[4] = {};
    float denom = 0.f;
    for (int base = ro; base < re; base += 32) {
        int idx = base + lane;
        float ea = 0.f; int s = 0;
        if (idx < re) {
            s = csr_src[idx];
            ea = __expf(lrelu(als[s] + aldh));
        }
        denom += ea;
        sh_ea[w][lane] = ea;
        sh_s [w][lane] = s;
        __syncwarp();

        int cnt = min(32, re - base);
        int nquad = (cnt + 3) >> 2;
        #pragma unroll 4
        for (int j = 0; j < nquad; j++) {
            int jj = 4*j + grp;
            float wgt = sh_ea[w][jj];
            int   sj  = sh_s [w][jj];
            float4 xv = *(const float4*)(hs + (size_t)sj * OUTC + q*4);
            acc[0] = fmaf(wgt, xv.x, acc[0]);
            acc[1] = fmaf(wgt, xv.y, acc[1]);
            acc[2] = fmaf(wgt, xv.z, acc[2]);
            acc[3] = fmaf(wgt, xv.w, acc[3]);
        }
        __syncwarp();
    }
    #pragma unroll
    for (int c = 0; c < 4; c++) {
        acc[c] += __shfl_xor_sync(0xffffffffu, acc[c], 8);
        acc[c] += __shfl_xor_sync(0xffffffffu, acc[c], 16);
    }
    #pragma unroll
    for (int o = 16; o; o >>= 1) denom += __shfl_xor_sync(0xffffffffu, denom, o);
    float inv = 1.f / (denom + 1e-16f);

    if (grp == 0) {
        float4 bv = *(const float4*)&bias[q*4];
        float4 o4 = make_float4(acc[0]*inv + bv.x, acc[1]*inv + bv.y,
                                acc[2]*inv + bv.z, acc[3]*inv + bv.w);
        *(float4*)&out[(size_t)d*OUTC + q*4] = o4;
    }
}

// =====================================================================
// Host-side orchestration
// =====================================================================
extern "C" void kernel_launch(void* const* d_in, const int* in_sizes, int n_in,
                              void* d_out, int out_size)
{
    const float* x_user   = (const float*)d_in[0];
    const float* x_item   = (const float*)d_in[1];
    const int*   e_u2i    = (const int*)  d_in[2];
    const int*   e_i2u    = (const int*)  d_in[3];
    const float* p_user_w = (const float*)d_in[4];
    const float* p_user_b = (const float*)d_in[5];
    const float* p_item_w = (const float*)d_in[6];
    const float* p_item_b = (const float*)d_in[7];
    const float* l0u_ws = (const float*)d_in[8];
    const float* l0u_wd = (const float*)d_in[9];
    const float* l0u_as = (const float*)d_in[10];
    const float* l0u_ad = (const float*)d_in[11];
    const float* l0u_b  = (const float*)d_in[12];
    const float* l0i_ws = (const float*)d_in[13];
    const float* l0i_wd = (const float*)d_in[14];
    const float* l0i_as = (const float*)d_in[15];
    const float* l0i_ad = (const float*)d_in[16];
    const float* l0i_b  = (const float*)d_in[17];
    const float* l1u_ws = (const float*)d_in[18];
    const float* l1u_wd = (const float*)d_in[19];
    const float* l1u_as = (const float*)d_in[20];
    const float* l1u_ad = (const float*)d_in[21];
    const float* l1u_b  = (const float*)d_in[22];
    const float* l1i_ws = (const float*)d_in[23];
    const float* l1i_wd = (const float*)d_in[24];
    const float* l1i_as = (const float*)d_in[25];
    const float* l1i_ad = (const float*)d_in[26];
    const float* l1i_b  = (const float*)d_in[27];

    float *hu, *hi, *hs, *hs2, *hu1, *al0, *al1, *vbuf;
    int *cnt2, *rank_u2i, *rank_i2u, *row_u2i, *row_i2u, *src_u2i, *src_i2u;
    cudaGetSymbolAddress((void**)&hu,  g_hu);
    cudaGetSymbolAddress((void**)&hi,  g_hi);
    cudaGetSymbolAddress((void**)&hs,  g_hs);
    cudaGetSymbolAddress((void**)&hs2, g_hs2);
    cudaGetSymbolAddress((void**)&hu1, g_hu1);
    cudaGetSymbolAddress((void**)&al0, g_al0);
    cudaGetSymbolAddress((void**)&al1, g_al1);
    cudaGetSymbolAddress((void**)&vbuf, g_vbuf);
    cudaGetSymbolAddress((void**)&cnt2,     g_cnt);
    cudaGetSymbolAddress((void**)&rank_u2i, g_rank_u2i);
    cudaGetSymbolAddress((void**)&rank_i2u, g_rank_i2u);
    cudaGetSymbolAddress((void**)&row_u2i,  g_row_u2i);
    cudaGetSymbolAddress((void**)&row_i2u,  g_row_i2u);
    cudaGetSymbolAddress((void**)&src_u2i,  g_src_u2i);
    cudaGetSymbolAddress((void**)&src_i2u,  g_src_i2u);

    const int N = N_NODES, E = E_EDGES;
    float* out_u = (float*)d_out;
    float* out_i = (float*)d_out + (size_t)N * OUTC;

    const int MB = (N + 127) / 128;
    const int WG2 = (2*N + 3) / 4;

    float* vsU0 = vbuf + 0*512;  float* vdU0 = vbuf + 1*512;
    float* vsI0 = vbuf + 2*512;  float* vdI0 = vbuf + 3*512;
    float* vsU1 = vbuf + 4*512;  float* vdU1 = vbuf + 5*512;
    float* vsI1 = vbuf + 6*512;  float* vdI1 = vbuf + 7*512;
    float* alA = al0 + 0*4*N;  float* alB = al0 + 1*4*N;
    float* alC = al0 + 2*4*N;  float* alD = al0 + 3*4*N;
    float* al1A = al1 + 0*N;  float* al1B = al1 + 1*N;
    float* al1C = al1 + 2*N;  float* al1D = al1 + 3*N;
    float* l1hsA = hu1;
    float* l1hsB = hu1 + (size_t)N * OUTC;

    // ---- fork: two CSR chains on two side streams, concurrent with prep+GEMM ----
    cudaEventRecord(g_evF, 0);
    cudaStreamWaitEvent(g_s2, g_evF, 0);
    cudaStreamWaitEvent(g_s3, g_evF, 0);

    // stream 2: u2i CSR
    hist1<<<(E/2 + 255)/256, 256, 0, g_s2>>>(e_u2i + E, cnt2, rank_u2i, E);
    scan1<<<1, 1024, 0, g_s2>>>(cnt2, row_u2i, N);
    fill1<<<(E/8 + 255)/256, 256, 0, g_s2>>>(e_u2i, e_u2i + E, rank_u2i, row_u2i,
                                             src_u2i, E);
    cudaEventRecord(g_evJ2, g_s2);

    // stream 3: i2u CSR
    hist1<<<(E/2 + 255)/256, 256, 0, g_s3>>>(e_i2u + E, cnt2 + N, rank_i2u, E);
    scan1<<<1, 1024, 0, g_s3>>>(cnt2 + N, row_i2u, N);
    fill1<<<(E/8 + 255)/256, 256, 0, g_s3>>>(e_i2u, e_i2u + E, rank_i2u, row_i2u,
                                             src_i2u, E);
    cudaEventRecord(g_evJ3, g_s3);

    // main stream: warp-parallel prep (1024 warps)
    {
        PrepJobs pj;
        pj.ws[0]=l0u_ws; pj.as_[0]=l0u_as; pj.wd[0]=l0u_wd; pj.ad_[0]=l0u_ad;
        pj.vs[0]=vsU0; pj.vd[0]=vdU0; pj.H[0]=HEADS; pj.C[0]=HID;
        pj.ws[1]=l0i_ws; pj.as_[1]=l0i_as; pj.wd[1]=l0i_wd; pj.ad_[1]=l0i_ad;
        pj.vs[1]=vsI0; pj.vd[1]=vdI0; pj.H[1]=HEADS; pj.C[1]=HID;
        pj.ws[2]=l1u_ws; pj.as_[2]=l1u_as; pj.wd[2]=l1u_wd; pj.ad_[2]=l1u_ad;
        pj.vs[2]=vsU1; pj.vd[2]=vdU1; pj.H[2]=1; pj.C[2]=OUTC;
        pj.ws[3]=l1i_ws; pj.as_[3]=l1i_as; pj.wd[3]=l1i_wd; pj.ad_[3]=l1i_ad;
        pj.vs[3]=vsI1; pj.vd[3]=vdI1; pj.H[3]=1; pj.C[3]=OUTC;
        prep_warp<<<128, 256>>>(pj);
    }

    // main stream: both projections + ELU + fused l0 logits (z=2)
    {
        GemmJobs j = {};
        j.A[0]=x_user;  j.B[0]=p_user_w; j.bias[0]=p_user_b; j.C[0]=hu;
        j.vs[0]=vsU0; j.vd[0]=vdI0; j.alS[0]=alA; j.alD[0]=alD;
        j.A[1]=x_item;  j.B[1]=p_item_w; j.bias[1]=p_item_b; j.C[1]=hi;
        j.vs[1]=vdU0; j.vd[1]=vsI0; j.alS[1]=alB; j.alD[1]=alC;
        mma_gemm_proj<<<dim3(1, MB, 2), 256>>>(j, N);
    }

    // ---- join both side chains ----
    cudaStreamWaitEvent(0, g_evJ2, 0);
    cudaStreamWaitEvent(0, g_evJ3, 0);

    // both layer-0 aggregations (one launch)
    gat_agg_l0_2<<<WG2, 128>>>(row_u2i, src_u2i, alA, alB, hu, hs,
                               row_i2u, src_i2u, alC, alD, hi, hs2, N);

    // FUSED: head-GEMMs + ELU + l1 logits + l1 GEMM (one launch, z=2)
    {
        FuseJobs f = {};
        f.A[0]=hs;  f.W1[0]=l0u_ws; f.b1[0]=l0u_b;
        f.vs[0]=vdU1; f.vd[0]=vsI1; f.alS[0]=al1B; f.alD[0]=al1C;
        f.W2[0]=l1i_ws; f.C2[0]=l1hsB;
        f.A[1]=hs2; f.W1[1]=l0i_ws; f.b1[1]=l0i_b;
        f.vs[1]=vsU1; f.vd[1]=vdI1; f.alS[1]=al1A; f.alD[1]=al1D;
        f.W2[1]=l1u_ws; f.C2[1]=l1hsA;
        head_l1_gemm<<<dim3(1, MB, 2), 256, 72704>>>(f, N);
    }

    // both layer-1 aggregations (one launch)
    gat_agg_l1_2<<<WG2, 128>>>(row_u2i, src_u2i, al1A, al1B, l1hsA, l1u_b, out_i,
                               row_i2u, src_i2u, al1C, al1D, l1hsB, l1i_b, out_u, N);
}

// round 16
// speedup vs baseline: 1.1325x; 1.1325x over previous
#include <cuda_runtime.h>
#include <cstdint>
#include <math.h>
#include <float.h>

#define N_NODES 50000
#define E_EDGES 800000
#define F_IN    128
#define HID     64
#define HEADS   4
#define OUTC    32
#define HC0     (HEADS*HID)   /* 256 */

// ---------------- scratch (static device globals; no allocation) ----------------
__device__ float g_hu [N_NODES * HID];
__device__ float g_hi [N_NODES * HID];
__device__ float g_hs [N_NODES * HC0];      // u2i agg scratch
__device__ float g_hs2[N_NODES * HC0];      // i2u agg scratch
__device__ float g_hu1[N_NODES * HC0];      // l1 GEMM outputs (2 x [N,32]) live here
__device__ float g_al0[16 * N_NODES];       // l0 logits: [A|B|C|D], each [N*4]
__device__ float g_al1[4 * N_NODES];        // l1 logits: [A|B|C|D], each [N]
__device__ float g_vbuf[8 * 512];
__device__ int   g_cnt [2 * N_NODES];
__device__ int   g_rank_u2i[E_EDGES];
__device__ int   g_rank_i2u[E_EDGES];
__device__ int   g_row_u2i[N_NODES + 1];
__device__ int   g_row_i2u[N_NODES + 1];
__device__ int   g_src_u2i[E_EDGES];
__device__ int   g_src_i2u[E_EDGES];

__device__ __forceinline__ float lrelu(float a) { return (a > 0.f) ? a : 0.2f * a; }

__device__ __forceinline__ uint32_t f2tf32(float f) {
    uint32_t u;
    asm("cvt.rna.tf32.f32 %0, %1;" : "=r"(u) : "f"(f));
    return u;
}
__device__ __forceinline__ void mma_tf32(float c[4], const uint32_t a[4],
                                         uint32_t b0, uint32_t b1) {
    asm volatile("mma.sync.aligned.m16n8k8.row.col.f32.tf32.tf32.f32 "
        "{%0,%1,%2,%3}, {%4,%5,%6,%7}, {%8,%9}, {%0,%1,%2,%3};"
        : "+f"(c[0]), "+f"(c[1]), "+f"(c[2]), "+f"(c[3])
        : "r"(a[0]), "r"(a[1]), "r"(a[2]), "r"(a[3]), "r"(b0), "r"(b1));
}

// ---------------- job descriptors ----------------
struct GemmJobs {
    const float* A[2];
    const float* B[2];
    const float* bias[2];
    float*       C[2];
    const float* vs[2];
    const float* vd[2];
    float*       alS[2];
    float*       alD[2];
};
struct FuseJobs {
    const float* A[2];
    const float* W1[2];
    const float* b1[2];
    const float* vs[2];
    const float* vd[2];
    float*       alS[2];
    float*       alD[2];
    const float* W2[2];
    float*       C2[2];
};

// =====================================================================
// Projection GEMM (tf32): C = ELU(A[M,128] @ B[128,64] + bias),
// fused layer-0 logit dots (4 heads each side, atomicAdd).
// =====================================================================
__global__ __launch_bounds__(256)
void mma_gemm_proj(GemmJobs jobs, int M)
{
    constexpr int BM = 128, BN = 64, BK = 32, K = F_IN;
    constexpr int THREADS = 256;
    constexpr int ASTR = 36;
    constexpr int BSTR = BN + 8;

    __shared__ uint32_t As[BM*ASTR];
    __shared__ uint32_t Bs[BK*BSTR];

    const int z = blockIdx.z;
    const float* __restrict__ A    = jobs.A[z];
    const float* __restrict__ B    = jobs.B[z];
    const float* __restrict__ bias = jobs.bias[z];
    float*       __restrict__ C    = jobs.C[z];
    const float* __restrict__ vs   = jobs.vs[z];
    const float* __restrict__ vd   = jobs.vd[z];
    float*       __restrict__ alS  = jobs.alS[z];
    float*       __restrict__ alD  = jobs.alD[z];

    const int tid  = threadIdx.x;
    const int wid  = tid >> 5;
    const int lane = tid & 31;
    const int g = lane >> 2, t = lane & 3;
    const int warpM = wid & 3;
    const int warpN = wid >> 2;
    const int rowBase = blockIdx.y * BM;

    float acc[2][4][4] = {};

    for (int k0 = 0; k0 < K; k0 += BK) {
        #pragma unroll
        for (int it = 0; it < (BM*BK/4)/THREADS; it++) {
            int idx = tid + it*THREADS;
            int m  = idx >> 3;
            int kv = idx & 7;
            int gm = rowBase + m;
            float4 v = make_float4(0.f,0.f,0.f,0.f);
            if (gm < M) v = *(const float4*)&A[(size_t)gm*K + k0 + kv*4];
            *(uint4*)&As[m*ASTR + kv*4] =
                make_uint4(f2tf32(v.x), f2tf32(v.y), f2tf32(v.z), f2tf32(v.w));
        }
        #pragma unroll
        for (int it = 0; it < (BK*BN/4)/THREADS; it++) {
            int idx = tid + it*THREADS;
            int kk = idx / (BN/4);
            int nv = idx % (BN/4);
            float4 v = *(const float4*)&B[(size_t)(k0+kk)*BN + nv*4];
            *(uint4*)&Bs[kk*BSTR + nv*4] =
                make_uint4(f2tf32(v.x), f2tf32(v.y), f2tf32(v.z), f2tf32(v.w));
        }
        __syncthreads();

        #pragma unroll
        for (int ks = 0; ks < BK/8; ks++) {
            int kb = ks*8;
            uint32_t a[2][4];
            #pragma unroll
            for (int mf = 0; mf < 2; mf++) {
                int m0 = warpM*32 + mf*16 + g;
                a[mf][0] = As[m0*ASTR     + kb + t];
                a[mf][1] = As[(m0+8)*ASTR + kb + t];
                a[mf][2] = As[m0*ASTR     + kb + t + 4];
                a[mf][3] = As[(m0+8)*ASTR + kb + t + 4];
            }
            #pragma unroll
            for (int nf = 0; nf < 4; nf++) {
                int n0 = warpN*32 + nf*8 + g;
                uint32_t b0 = Bs[(kb+t)*BSTR   + n0];
                uint32_t b1 = Bs[(kb+t+4)*BSTR + n0];
                mma_tf32(acc[0][nf], a[0], b0, b1);
                mma_tf32(acc[1][nf], a[1], b0, b1);
            }
        }
        __syncthreads();
    }

    #pragma unroll
    for (int mf = 0; mf < 2; mf++) {
        #pragma unroll
        for (int rr = 0; rr < 2; rr++) {
            int row = rowBase + warpM*32 + mf*16 + rr*8 + g;
            bool ok = row < M;
            float aS[4] = {}, aD[4] = {};
            #pragma unroll
            for (int nf = 0; nf < 4; nf++) {
                int col = warpN*32 + nf*8 + 2*t;
                float v0 = acc[mf][nf][rr*2 + 0] + bias[col];
                float v1 = acc[mf][nf][rr*2 + 1] + bias[col + 1];
                v0 = (v0 > 0.f) ? v0 : (expf(v0) - 1.f);
                v1 = (v1 > 0.f) ? v1 : (expf(v1) - 1.f);
                if (ok) *(float2*)&C[(size_t)row*BN + col] = make_float2(v0, v1);
                #pragma unroll
                for (int h = 0; h < 4; h++) {
                    aS[h] = fmaf(v0, vs[col*4 + h],     aS[h]);
                    aS[h] = fmaf(v1, vs[(col+1)*4 + h], aS[h]);
                    aD[h] = fmaf(v0, vd[col*4 + h],     aD[h]);
                    aD[h] = fmaf(v1, vd[(col+1)*4 + h], aD[h]);
                }
            }
            #pragma unroll
            for (int h = 0; h < 4; h++) {
                aS[h] += __shfl_xor_sync(0xffffffffu, aS[h], 1);
                aS[h] += __shfl_xor_sync(0xffffffffu, aS[h], 2);
                aD[h] += __shfl_xor_sync(0xffffffffu, aD[h], 1);
                aD[h] += __shfl_xor_sync(0xffffffffu, aD[h], 2);
            }
            if (t == 0 && ok) {
                #pragma unroll
                for (int h = 0; h < 4; h++) {
                    atomicAdd(&alS[row*4 + h], aS[h]);
                    atomicAdd(&alD[row*4 + h], aD[h]);
                }
            }
        }
    }
}

// =====================================================================
// FUSED head-GEMM chain + l1-GEMM (hi1/hu1 never touch global memory).
// =====================================================================
__global__ __launch_bounds__(256)
void head_l1_gemm(FuseJobs jobs, int M)
{
    constexpr int BM = 128;
    constexpr int ASTR = 36, BSTR = 72, C1STR = 68, B2STR = 40;
    extern __shared__ uint32_t sm[];
    uint32_t* As  = sm;
    uint32_t* Bs  = As  + BM*ASTR;
    uint32_t* C1s = Bs  + 32*BSTR;
    uint32_t* B2s = C1s + 128*C1STR;

    const int z = blockIdx.z;
    const float* __restrict__ A   = jobs.A[z];
    const float* __restrict__ W1  = jobs.W1[z];
    const float* __restrict__ b1  = jobs.b1[z];
    const float* __restrict__ vs  = jobs.vs[z];
    const float* __restrict__ vd  = jobs.vd[z];
    float*       __restrict__ alS = jobs.alS[z];
    float*       __restrict__ alD = jobs.alD[z];
    const float* __restrict__ W2  = jobs.W2[z];
    float*       __restrict__ C2  = jobs.C2[z];

    const int tid  = threadIdx.x;
    const int wid  = tid >> 5;
    const int lane = tid & 31;
    const int g = lane >> 2, t = lane & 3;
    const int warpM = wid & 3;
    const int warpN = wid >> 2;
    const int rowBase = blockIdx.y * BM;

    float acc2[2][2][4] = {};
    float aS[2][2] = {}, aD[2][2] = {};

    for (int h = 0; h < 4; h++) {
        float acc[2][4][4] = {};
        for (int k0 = 0; k0 < 64; k0 += 32) {
            #pragma unroll
            for (int it = 0; it < 4; it++) {
                int idx = tid + it*256;
                int m  = idx >> 3;
                int kv = idx & 7;
                int gm = rowBase + m;
                float4 v = make_float4(0.f,0.f,0.f,0.f);
                if (gm < M) v = *(const float4*)&A[(size_t)gm*HC0 + h*64 + k0 + kv*4];
                *(uint4*)&As[m*ASTR + kv*4] =
                    make_uint4(f2tf32(v.x), f2tf32(v.y), f2tf32(v.z), f2tf32(v.w));
            }
            #pragma unroll
            for (int it = 0; it < 2; it++) {
                int idx = tid + it*256;
                int kk = idx / 16;
                int nv = idx % 16;
                float4 v = *(const float4*)&W1[(size_t)(k0+kk)*HC0 + h*64 + nv*4];
                *(uint4*)&Bs[kk*BSTR + nv*4] =
                    make_uint4(f2tf32(v.x), f2tf32(v.y), f2tf32(v.z), f2tf32(v.w));
            }
            __syncthreads();
            #pragma unroll
            for (int ks = 0; ks < 4; ks++) {
                int kb = ks*8;
                uint32_t a[2][4];
                #pragma unroll
                for (int mf = 0; mf < 2; mf++) {
                    int m0 = warpM*32 + mf*16 + g;
                    a[mf][0] = As[m0*ASTR     + kb + t];
                    a[mf][1] = As[(m0+8)*ASTR + kb + t];
                    a[mf][2] = As[m0*ASTR     + kb + t + 4];
                    a[mf][3] = As[(m0+8)*ASTR + kb + t + 4];
                }
                #pragma unroll
                for (int nf = 0; nf < 4; nf++) {
                    int n0 = warpN*32 + nf*8 + g;
                    uint32_t b0 = Bs[(kb+t)*BSTR   + n0];
                    uint32_t bb = Bs[(kb+t+4)*BSTR + n0];
                    mma_tf32(acc[0][nf], a[0], b0, bb);
                    mma_tf32(acc[1][nf], a[1], b0, bb);
                }
            }
            __syncthreads();
        }

        #pragma unroll
        for (int mf = 0; mf < 2; mf++) {
            #pragma unroll
            for (int rr = 0; rr < 2; rr++) {
                int rl = warpM*32 + mf*16 + rr*8 + g;
                #pragma unroll
                for (int nf = 0; nf < 4; nf++) {
                    int col = warpN*32 + nf*8 + 2*t;
                    float v0 = acc[mf][nf][rr*2 + 0] + b1[h*64 + col];
                    float v1 = acc[mf][nf][rr*2 + 1] + b1[h*64 + col + 1];
                    v0 = (v0 > 0.f) ? v0 : (expf(v0) - 1.f);
                    v1 = (v1 > 0.f) ? v1 : (expf(v1) - 1.f);
                    aS[mf][rr] = fmaf(v0, vs[h*64 + col],     aS[mf][rr]);
                    aS[mf][rr] = fmaf(v1, vs[h*64 + col + 1], aS[mf][rr]);
                    aD[mf][rr] = fmaf(v0, vd[h*64 + col],     aD[mf][rr]);
                    aD[mf][rr] = fmaf(v1, vd[h*64 + col + 1], aD[mf][rr]);
                    C1s[rl*C1STR + col]     = f2tf32(v0);
                    C1s[rl*C1STR + col + 1] = f2tf32(v1);
                }
            }
        }
        #pragma unroll
        for (int it = 0; it < 2; it++) {
            int idx = tid + it*256;
            int kk = idx / 8;
            int nv = idx % 8;
            float4 v = *(const float4*)&W2[(size_t)(h*64 + kk)*OUTC + nv*4];
            *(uint4*)&B2s[kk*B2STR + nv*4] =
                make_uint4(f2tf32(v.x), f2tf32(v.y), f2tf32(v.z), f2tf32(v.w));
        }
        __syncthreads();

        #pragma unroll
        for (int ks = 0; ks < 8; ks++) {
            int kb = ks*8;
            uint32_t a2[2][4];
            #pragma unroll
            for (int mf = 0; mf < 2; mf++) {
                int m0 = warpM*32 + mf*16 + g;
                a2[mf][0] = C1s[m0*C1STR     + kb + t];
                a2[mf][1] = C1s[(m0+8)*C1STR + kb + t];
                a2[mf][2] = C1s[m0*C1STR     + kb + t + 4];
                a2[mf][3] = C1s[(m0+8)*C1STR + kb + t + 4];
            }
            #pragma unroll
            for (int nf2 = 0; nf2 < 2; nf2++) {
                int n0 = warpN*16 + nf2*8 + g;
                uint32_t b0 = B2s[(kb+t)*B2STR   + n0];
                uint32_t bb = B2s[(kb+t+4)*B2STR + n0];
                mma_tf32(acc2[0][nf2], a2[0], b0, bb);
                mma_tf32(acc2[1][nf2], a2[1], b0, bb);
            }
        }
        __syncthreads();
    }

    #pragma unroll
    for (int mf = 0; mf < 2; mf++) {
        #pragma unroll
        for (int rr = 0; rr < 2; rr++) {
            int row = rowBase + warpM*32 + mf*16 + rr*8 + g;
            bool ok = row < M;
            float s = aS[mf][rr], dd = aD[mf][rr];
            s  += __shfl_xor_sync(0xffffffffu, s, 1);
            s  += __shfl_xor_sync(0xffffffffu, s, 2);
            dd += __shfl_xor_sync(0xffffffffu, dd, 1);
            dd += __shfl_xor_sync(0xffffffffu, dd, 2);
            if (t == 0 && ok) {
                atomicAdd(&alS[row], s);
                atomicAdd(&alD[row], dd);
            }
            #pragma unroll
            for (int nf2 = 0; nf2 < 2; nf2++) {
                int col = warpN*16 + nf2*8 + 2*t;
                float v0 = acc2[mf][nf2][rr*2 + 0];
                float v1 = acc2[mf][nf2][rr*2 + 1];
                if (ok) *(float2*)&C2[(size_t)row*OUTC + col] = make_float2(v0, v1);
            }
        }
    }
}

// ---------------- side stream + events + smem attr (created pre-checkpoint) -----
static cudaStream_t g_s2;
static cudaEvent_t  g_evF, g_evJ;
static int g_stream_init = []() {
    cudaStreamCreateWithFlags(&g_s2, cudaStreamNonBlocking);
    cudaEventCreateWithFlags(&g_evF, cudaEventDisableTiming);
    cudaEventCreateWithFlags(&g_evJ, cudaEventDisableTiming);
    cudaFuncSetAttribute(head_l1_gemm, cudaFuncAttributeMaxDynamicSharedMemorySize, 72704);
    return 0;
}();

// =====================================================================
// Zero logits + WARP-PARALLEL attention-vector prep, single launch.
// Blocks [0, ZB) zero al0/al1.
// Blocks [ZB, ZB+128): 8 warps each -> 1024 warps = 4 jobs x 256 outputs;
// lanes split the C dimension, shuffle-reduce.
// =====================================================================
struct PrepJobs {
    const float* ws[4]; const float* as_[4];
    const float* wd[4]; const float* ad_[4];
    float* vs[4]; float* vd[4];
    int H[4]; int C[4];
};

__global__ void zero_prep(float* __restrict__ al0, float* __restrict__ al1,
                          int ZB, PrepJobs pj)
{
    int b = blockIdx.x;
    if (b < ZB) {
        int i = b * blockDim.x + threadIdx.x;
        if (i < 4*N_NODES)  al1[i] = 0.f;
        if (i < 16*N_NODES) al0[i] = 0.f;
        return;
    }
    int gw   = (b - ZB) * 8 + (threadIdx.x >> 5);   // 0..1023
    int lane = threadIdx.x & 31;
    int j    = gw >> 8;          // job 0..3
    int idx  = gw & 255;         // output index (all jobs have 256 outputs)
    int H = pj.H[j], C = pj.C[j];
    int k = idx / H, h = idx % H;
    const float* wsp = pj.ws[j] + (size_t)k*(H*C) + h*C;
    const float* wdp = pj.wd[j] + (size_t)k*(H*C) + h*C;
    const float* asp = pj.as_[j] + h*C;
    const float* adp = pj.ad_[j] + h*C;
    float s1 = 0.f, s2 = 0.f;
    for (int c = lane; c < C; c += 32) {
        s1 = fmaf(wsp[c], asp[c], s1);
        s2 = fmaf(wdp[c], adp[c], s2);
    }
    #pragma unroll
    for (int o = 16; o; o >>= 1) {
        s1 += __shfl_xor_sync(0xffffffffu, s1, o);
        s2 += __shfl_xor_sync(0xffffffffu, s2, o);
    }
    if (lane == 0) {
        pj.vs[j][idx] = s1;     // idx == k*H + h
        pj.vd[j][idx] = s2;
    }
}

// =====================================================================
// CSR build (side stream): zero cnt -> histogram(rank) -> scan -> rank fill
// =====================================================================
__global__ void zero_cnt(int* __restrict__ cnt2) {
    int i = blockIdx.x * blockDim.x + threadIdx.x;
    if (i < 2*N_NODES) cnt2[i] = 0;
}
__global__ void hist2(const int* __restrict__ dst1, const int* __restrict__ dst2,
                      int* __restrict__ cnt2,
                      int* __restrict__ rank1, int* __restrict__ rank2, int E)
{
    int e = blockIdx.x * blockDim.x + threadIdx.x;
    if (e < E)        rank1[e]     = atomicAdd(&cnt2[dst1[e]], 1);
    else if (e < 2*E) rank2[e - E] = atomicAdd(&cnt2[N_NODES + dst2[e - E]], 1);
}
__global__ void scan2(const int* __restrict__ cnt2,
                      int* __restrict__ row1, int* __restrict__ row2, int n)
{
    const int set = blockIdx.x;
    const int* cnt = cnt2 + set * n;
    int* row = set ? row2 : row1;

    __shared__ int wsum[32];
    __shared__ int s_carry;
    int tid = threadIdx.x, lane = tid & 31, warp = tid >> 5;
    if (tid == 0) s_carry = 0;
    __syncthreads();
    for (int base = 0; base < n; base += 1024) {
        int v = (base + tid < n) ? cnt[base + tid] : 0;
        int s = v;
        #pragma unroll
        for (int o = 1; o < 32; o <<= 1) {
            int t = __shfl_up_sync(0xffffffffu, s, o);
            if (lane >= o) s += t;
        }
        if (lane == 31) wsum[warp] = s;
        __syncthreads();
        if (warp == 0) {
            int ws = wsum[lane];
            #pragma unroll
            for (int o = 1; o < 32; o <<= 1) {
                int t = __shfl_up_sync(0xffffffffu, ws, o);
                if (lane >= o) ws += t;
            }
            wsum[lane] = ws;
        }
        __syncthreads();
        int carry = s_carry;
        int incl  = s + (warp > 0 ? wsum[warp - 1] : 0);
        if (base + tid < n) row[base + tid] = carry + incl - v;
        __syncthreads();
        if (tid == 1023) s_carry = carry + wsum[31];
        __syncthreads();
    }
    if (tid == 0) row[n] = s_carry;
}
// 4 edges per thread, int4 vector loads (E % 4 == 0)
__global__ void csr_fill2(const int* __restrict__ s1, const int* __restrict__ d1,
                          const int* __restrict__ s2, const int* __restrict__ d2,
                          const int* __restrict__ rank1, const int* __restrict__ rank2,
                          const int* __restrict__ row1, const int* __restrict__ row2,
                          int* __restrict__ out1, int* __restrict__ out2, int E)
{
    int e = 4 * (blockIdx.x * blockDim.x + threadIdx.x);
    if (e < E) {
        int4 dv = *(const int4*)&d1[e];
        int4 rv = *(const int4*)&rank1[e];
        int4 sv = *(const int4*)&s1[e];
        out1[row1[dv.x] + rv.x] = sv.x;
        out1[row1[dv.y] + rv.y] = sv.y;
        out1[row1[dv.z] + rv.z] = sv.z;
        out1[row1[dv.w] + rv.w] = sv.w;
    } else if (e < 2*E) {
        int ee = e - E;
        int4 dv = *(const int4*)&d2[ee];
        int4 rv = *(const int4*)&rank2[ee];
        int4 sv = *(const int4*)&s2[ee];
        out2[row2[dv.x] + rv.x] = sv.x;
        out2[row2[dv.y] + rv.y] = sv.y;
        out2[row2[dv.z] + rv.z] = sv.z;
        out2[row2[dv.w] + rv.w] = sv.w;
    }
}

// =====================================================================
// Layer-0 aggregation (both directions), single pass, 2 edges/iter.
// =====================================================================
__global__ void gat_agg_l0_2(const int* __restrict__ rowA, const int* __restrict__ srcA,
                             const float* __restrict__ alsA, const float* __restrict__ aldA,
                             const float* __restrict__ xA, float* __restrict__ outA,
                             const int* __restrict__ rowB, const int* __restrict__ srcB,
                             const float* __restrict__ alsB, const float* __restrict__ aldB,
                             const float* __restrict__ xB, float* __restrict__ outB,
                             int N)
{
    __shared__ float4 sh_ea[4][32];
    __shared__ int    sh_s [4][32];

    int gw   = (blockIdx.x * blockDim.x + threadIdx.x) >> 5;
    int w    = (threadIdx.x >> 5) & 3;
    int lane = threadIdx.x & 31;
    int half = lane >> 4;
    int q    = lane & 15;
    if (gw >= 2*N) return;
    int dir = (gw >= N);
    int d   = dir ? gw - N : gw;
    const int*   row_ptr = dir ? rowB : rowA;
    const int*   csr_src = dir ? srcB : srcA;
    const float* als     = dir ? alsB : alsA;
    const float* ald     = dir ? aldB : aldA;
    const float* x       = dir ? xB   : xA;
    float*       agg     = dir ? outB : outA;

    int ro = row_ptr[d], re = row_ptr[d + 1];
    float4 adv = ((const float4*)ald)[d];
    float ad[4] = {adv.x, adv.y, adv.z, adv.w};

    float acc[4][4] = {};
    float den[4] = {};

    for (int base = ro; base < re; base += 32) {
        int idx = base + lane;
        int s = 0;
        float4 ea4 = make_float4(0.f, 0.f, 0.f, 0.f);
        if (idx < re) {
            s = csr_src[idx];
            float4 av = ((const float4*)als)[s];
            ea4.x = __expf(lrelu(av.x + ad[0]));
            ea4.y = __expf(lrelu(av.y + ad[1]));
            ea4.z = __expf(lrelu(av.z + ad[2]));
            ea4.w = __expf(lrelu(av.w + ad[3]));
        }
        den[0] += ea4.x; den[1] += ea4.y; den[2] += ea4.z; den[3] += ea4.w;
        sh_ea[w][lane] = ea4;
        sh_s [w][lane] = s;
        __syncwarp();

        int cnt = min(32, re - base);
        int npair = (cnt + 1) >> 1;
        #pragma unroll 4
        for (int j = 0; j < npair; j++) {
            int jj = 2*j + half;
            float4 e4 = sh_ea[w][jj];
            int    sj = sh_s [w][jj];
            float  e[4] = {e4.x, e4.y, e4.z, e4.w};
            float4 xv = *(const float4*)(x + (size_t)sj * HID + q*4);
            float  xr[4] = {xv.x, xv.y, xv.z, xv.w};
            #pragma unroll
            for (int h = 0; h < 4; h++)
                #pragma unroll
                for (int c = 0; c < 4; c++)
                    acc[h][c] = fmaf(e[h], xr[c], acc[h][c]);
        }
        __syncwarp();
    }
    #pragma unroll
    for (int h = 0; h < 4; h++) {
        #pragma unroll
        for (int c = 0; c < 4; c++)
            acc[h][c] += __shfl_xor_sync(0xffffffffu, acc[h][c], 16);
        #pragma unroll
        for (int o = 16; o; o >>= 1)
            den[h] += __shfl_xor_sync(0xffffffffu, den[h], o);
    }

    int h0 = 2*half;
    #pragma unroll
    for (int hh = 0; hh < 2; hh++) {
        int h = h0 + hh;
        float inv = 1.f / (den[h] + 1e-16f);
        float4 o4 = make_float4(acc[h][0]*inv, acc[h][1]*inv,
                                acc[h][2]*inv, acc[h][3]*inv);
        *(float4*)&agg[(size_t)d*HC0 + h*HID + q*4] = o4;
    }
}

// =====================================================================
// Layer-1 aggregation (both directions), single pass, 4 edges/iter.
// =====================================================================
__global__ void gat_agg_l1_2(const int* __restrict__ rowA, const int* __restrict__ srcA,
                             const float* __restrict__ alsA, const float* __restrict__ aldA,
                             const float* __restrict__ hsA, const float* __restrict__ biasA,
                             float* __restrict__ outA,
                             const int* __restrict__ rowB, const int* __restrict__ srcB,
                             const float* __restrict__ alsB, const float* __restrict__ aldB,
                             const float* __restrict__ hsB, const float* __restrict__ biasB,
                             float* __restrict__ outB,
                             int N)
{
    __shared__ float sh_ea[4][32];
    __shared__ int   sh_s [4][32];

    int gw   = (blockIdx.x * blockDim.x + threadIdx.x) >> 5;
    int w    = (threadIdx.x >> 5) & 3;
    int lane = threadIdx.x & 31;
    int grp  = lane >> 3;
    int q    = lane & 7;
    if (gw >= 2*N) return;
    int dir = (gw >= N);
    int d   = dir ? gw - N : gw;
    const int*   row_ptr = dir ? rowB  : rowA;
    const int*   csr_src = dir ? srcB  : srcA;
    const float* als     = dir ? alsB  : alsA;
    const float* ald     = dir ? aldB  : aldA;
    const float* hs      = dir ? hsB   : hsA;
    const float* bias    = dir ? biasB : biasA;
    float*       out     = dir ? outB  : outA;

    int ro = row_ptr[d], re = row_ptr[d + 1];
    float aldh = ald[d];

    float acc[4] = {};
    float denom = 0.f;
    for (int base = ro; base < re; base += 32) {
        int idx = base + lane;
        float ea = 0.f; int s = 0;
        if (idx < re) {
            s = csr_src[idx];
            ea = __expf(lrelu(als[s] + aldh));
        }
        denom += ea;
        sh_ea[w][lane] = ea;
        sh_s [w][lane] = s;
        __syncwarp();

        int cnt = min(32, re - base);
        int nquad = (cnt + 3) >> 2;
        #pragma unroll 4
        for (int j = 0; j < nquad; j++) {
            int jj = 4*j + grp;
            float wgt = sh_ea[w][jj];
            int   sj  = sh_s [w][jj];
            float4 xv = *(const float4*)(hs + (size_t)sj * OUTC + q*4);
            acc[0] = fmaf(wgt, xv.x, acc[0]);
            acc[1] = fmaf(wgt, xv.y, acc[1]);
            acc[2] = fmaf(wgt, xv.z, acc[2]);
            acc[3] = fmaf(wgt, xv.w, acc[3]);
        }
        __syncwarp();
    }
    #pragma unroll
    for (int c = 0; c < 4; c++) {
        acc[c] += __shfl_xor_sync(0xffffffffu, acc[c], 8);
        acc[c] += __shfl_xor_sync(0xffffffffu, acc[c], 16);
    }
    #pragma unroll
    for (int o = 16; o; o >>= 1) denom += __shfl_xor_sync(0xffffffffu, denom, o);
    float inv = 1.f / (denom + 1e-16f);

    if (grp == 0) {
        float4 bv = *(const float4*)&bias[q*4];
        float4 o4 = make_float4(acc[0]*inv + bv.x, acc[1]*inv + bv.y,
                                acc[2]*inv + bv.z, acc[3]*inv + bv.w);
        *(float4*)&out[(size_t)d*OUTC + q*4] = o4;
    }
}

// =====================================================================
// Host-side orchestration
// =====================================================================
extern "C" void kernel_launch(void* const* d_in, const int* in_sizes, int n_in,
                              void* d_out, int out_size)
{
    const float* x_user   = (const float*)d_in[0];
    const float* x_item   = (const float*)d_in[1];
    const int*   e_u2i    = (const int*)  d_in[2];
    const int*   e_i2u    = (const int*)  d_in[3];
    const float* p_user_w = (const float*)d_in[4];
    const float* p_user_b = (const float*)d_in[5];
    const float* p_item_w = (const float*)d_in[6];
    const float* p_item_b = (const float*)d_in[7];
    const float* l0u_ws = (const float*)d_in[8];
    const float* l0u_wd = (const float*)d_in[9];
    const float* l0u_as = (const float*)d_in[10];
    const float* l0u_ad = (const float*)d_in[11];
    const float* l0u_b  = (const float*)d_in[12];
    const float* l0i_ws = (const float*)d_in[13];
    const float* l0i_wd = (const float*)d_in[14];
    const float* l0i_as = (const float*)d_in[15];
    const float* l0i_ad = (const float*)d_in[16];
    const float* l0i_b  = (const float*)d_in[17];
    const float* l1u_ws = (const float*)d_in[18];
    const float* l1u_wd = (const float*)d_in[19];
    const float* l1u_as = (const float*)d_in[20];
    const float* l1u_ad = (const float*)d_in[21];
    const float* l1u_b  = (const float*)d_in[22];
    const float* l1i_ws = (const float*)d_in[23];
    const float* l1i_wd = (const float*)d_in[24];
    const float* l1i_as = (const float*)d_in[25];
    const float* l1i_ad = (const float*)d_in[26];
    const float* l1i_b  = (const float*)d_in[27];

    float *hu, *hi, *hs, *hs2, *hu1, *al0, *al1, *vbuf;
    int *cnt2, *rank_u2i, *rank_i2u, *row_u2i, *row_i2u, *src_u2i, *src_i2u;
    cudaGetSymbolAddress((void**)&hu,  g_hu);
    cudaGetSymbolAddress((void**)&hi,  g_hi);
    cudaGetSymbolAddress((void**)&hs,  g_hs);
    cudaGetSymbolAddress((void**)&hs2, g_hs2);
    cudaGetSymbolAddress((void**)&hu1, g_hu1);
    cudaGetSymbolAddress((void**)&al0, g_al0);
    cudaGetSymbolAddress((void**)&al1, g_al1);
    cudaGetSymbolAddress((void**)&vbuf, g_vbuf);
    cudaGetSymbolAddress((void**)&cnt2,     g_cnt);
    cudaGetSymbolAddress((void**)&rank_u2i, g_rank_u2i);
    cudaGetSymbolAddress((void**)&rank_i2u, g_rank_i2u);
    cudaGetSymbolAddress((void**)&row_u2i,  g_row_u2i);
    cudaGetSymbolAddress((void**)&row_i2u,  g_row_i2u);
    cudaGetSymbolAddress((void**)&src_u2i,  g_src_u2i);
    cudaGetSymbolAddress((void**)&src_i2u,  g_src_i2u);

    const int N = N_NODES, E = E_EDGES;
    float* out_u = (float*)d_out;
    float* out_i = (float*)d_out + (size_t)N * OUTC;

    const int MB = (N + 127) / 128;
    const int WG2 = (2*N + 3) / 4;

    float* vsU0 = vbuf + 0*512;  float* vdU0 = vbuf + 1*512;
    float* vsI0 = vbuf + 2*512;  float* vdI0 = vbuf + 3*512;
    float* vsU1 = vbuf + 4*512;  float* vdU1 = vbuf + 5*512;
    float* vsI1 = vbuf + 6*512;  float* vdI1 = vbuf + 7*512;
    float* alA = al0 + 0*4*N;  float* alB = al0 + 1*4*N;
    float* alC = al0 + 2*4*N;  float* alD = al0 + 3*4*N;
    float* al1A = al1 + 0*N;  float* al1B = al1 + 1*N;
    float* al1C = al1 + 2*N;  float* al1D = al1 + 3*N;
    float* l1hsA = hu1;
    float* l1hsB = hu1 + (size_t)N * OUTC;

    // ---- fork: CSR chain on side stream, concurrent with prep + proj GEMM ----
    cudaEventRecord(g_evF, 0);
    cudaStreamWaitEvent(g_s2, g_evF, 0);

    zero_cnt <<<(2*N + 255)/256, 256, 0, g_s2>>>(cnt2);
    hist2    <<<(2*E + 255)/256, 256, 0, g_s2>>>(e_u2i + E, e_i2u + E, cnt2,
                                                 rank_u2i, rank_i2u, E);
    scan2    <<<2, 1024, 0, g_s2>>>(cnt2, row_u2i, row_i2u, N);
    csr_fill2<<<(2*E/4 + 255)/256, 256, 0, g_s2>>>(e_u2i, e_u2i + E, e_i2u, e_i2u + E,
                                                   rank_u2i, rank_i2u, row_u2i, row_i2u,
                                                   src_u2i, src_i2u, E);
    cudaEventRecord(g_evJ, g_s2);

    // main stream: zero logits + warp-parallel prep vectors (one launch)
    {
        PrepJobs pj;
        pj.ws[0]=l0u_ws; pj.as_[0]=l0u_as; pj.wd[0]=l0u_wd; pj.ad_[0]=l0u_ad;
        pj.vs[0]=vsU0; pj.vd[0]=vdU0; pj.H[0]=HEADS; pj.C[0]=HID;
        pj.ws[1]=l0i_ws; pj.as_[1]=l0i_as; pj.wd[1]=l0i_wd; pj.ad_[1]=l0i_ad;
        pj.vs[1]=vsI0; pj.vd[1]=vdI0; pj.H[1]=HEADS; pj.C[1]=HID;
        pj.ws[2]=l1u_ws; pj.as_[2]=l1u_as; pj.wd[2]=l1u_wd; pj.ad_[2]=l1u_ad;
        pj.vs[2]=vsU1; pj.vd[2]=vdU1; pj.H[2]=1; pj.C[2]=OUTC;
        pj.ws[3]=l1i_ws; pj.as_[3]=l1i_as; pj.wd[3]=l1i_wd; pj.ad_[3]=l1i_ad;
        pj.vs[3]=vsI1; pj.vd[3]=vdI1; pj.H[3]=1; pj.C[3]=OUTC;
        int ZB = (16*N + 255)/256;
        zero_prep<<<ZB + 128, 256>>>(al0, al1, ZB, pj);
    }

    // main stream: both projections + ELU + fused l0 logits (z=2)
    {
        GemmJobs j = {};
        j.A[0]=x_user;  j.B[0]=p_user_w; j.bias[0]=p_user_b; j.C[0]=hu;
        j.vs[0]=vsU0; j.vd[0]=vdI0; j.alS[0]=alA; j.alD[0]=alD;
        j.A[1]=x_item;  j.B[1]=p_item_w; j.bias[1]=p_item_b; j.C[1]=hi;
        j.vs[1]=vdU0; j.vd[1]=vsI0; j.alS[1]=alB; j.alD[1]=alC;
        mma_gemm_proj<<<dim3(1, MB, 2), 256>>>(j, N);
    }

    // ---- join ----
    cudaStreamWaitEvent(0, g_evJ, 0);

    // both layer-0 aggregations (one launch)
    gat_agg_l0_2<<<WG2, 128>>>(row_u2i, src_u2i, alA, alB, hu, hs,
                               row_i2u, src_i2u, alC, alD, hi, hs2, N);

    // FUSED: head-GEMMs + ELU + l1 logits + l1 GEMM (one launch, z=2)
    {
        FuseJobs f = {};
        f.A[0]=hs;  f.W1[0]=l0u_ws; f.b1[0]=l0u_b;
        f.vs[0]=vdU1; f.vd[0]=vsI1; f.alS[0]=al1B; f.alD[0]=al1C;
        f.W2[0]=l1i_ws; f.C2[0]=l1hsB;
        f.A[1]=hs2; f.W1[1]=l0i_ws; f.b1[1]=l0i_b;
        f.vs[1]=vsU1; f.vd[1]=vdI1; f.alS[1]=al1A; f.alD[1]=al1D;
        f.W2[1]=l1u_ws; f.C2[1]=l1hsA;
        head_l1_gemm<<<dim3(1, MB, 2), 256, 72704>>>(f, N);
    }

    // both layer-1 aggregations (one launch)
    gat_agg_l1_2<<<WG2, 128>>>(row_u2i, src_u2i, al1A, al1B, l1hsA, l1u_b, out_i,
                               row_i2u, src_i2u, al1C, al1D, l1hsB, l1i_b, out_u, N);
}